// round 1
// baseline (speedup 1.0000x reference)
#include <cuda_runtime.h>
#include <math.h>

// Problem constants
#define Bn 256
#define Dn 10
#define Mn 32
#define Pn 36
#define In 8
#define On 16

#define THREADS 320            // 10 warps: warp = d, lane = m

// Padded smem layouts (bank-conflict-free):
//  x row stride 292 floats (P*I=288 + 4)  -> lane word offset 4m mod 32: distinct 4-aligned groups per 8-lane phase for LDS.128
//  b row stride 37 floats  (P=36 + 1)     -> lane word offset 5m mod 32: all distinct (gcd(5,32)=1) for scalar LDS
#define XROW 292
#define BROW 37

#define XS_FLOATS (Mn * XROW)                 // 9344
#define BB_FLOATS (Dn * Mn * BROW)            // 11840
#define MX_FLOATS (Mn * BROW)                 // 1184
#define SMEM_FLOATS (XS_FLOATS + BB_FLOATS + 2 * MX_FLOATS)   // 23552 -> 94208 B

// s[d,o] = sum_m sum_i W[d,m,o,i]*xc[d,m,i]; warp-butterfly reduce over m (lane);
// then squash -> v (every lane ends with the full v[0..15]).
__device__ __forceinline__ void compute_v(const float4* __restrict__ Wdm,
                                          const float xc[In], float v[On]) {
#pragma unroll
    for (int o = 0; o < On; o++) {
        float4 w0 = __ldg(Wdm + 2 * o);
        float4 w1 = __ldg(Wdm + 2 * o + 1);
        v[o] = w0.x * xc[0] + w0.y * xc[1] + w0.z * xc[2] + w0.w * xc[3]
             + w1.x * xc[4] + w1.y * xc[5] + w1.z * xc[6] + w1.w * xc[7];
    }
#pragma unroll
    for (int off = 16; off; off >>= 1) {
#pragma unroll
        for (int o = 0; o < On; o++)
            v[o] += __shfl_xor_sync(0xffffffffu, v[o], off);
    }
    float sq = 0.f;
#pragma unroll
    for (int o = 0; o < On; o++) sq += v[o] * v[o];
    // squash: v = (sq/(1+sq)) * s / sqrt(sq + 1e-7)
    float k = sq / ((1.0f + sq) * sqrtf(sq + 1e-7f));
#pragma unroll
    for (int o = 0; o < On; o++) v[o] *= k;
}

// wv[i] = sum_o W[d,m,o,i] * v[o]   (all register-resident)
__device__ __forceinline__ void compute_wv(const float4* __restrict__ Wdm,
                                           const float v[On], float wv[In]) {
#pragma unroll
    for (int i = 0; i < In; i++) wv[i] = 0.f;
#pragma unroll
    for (int o = 0; o < On; o++) {
        float4 w0 = __ldg(Wdm + 2 * o);
        float4 w1 = __ldg(Wdm + 2 * o + 1);
        float vo = v[o];
        wv[0] += w0.x * vo; wv[1] += w0.y * vo; wv[2] += w0.z * vo; wv[3] += w0.w * vo;
        wv[4] += w1.x * vo; wv[5] += w1.y * vo; wv[6] += w1.z * vo; wv[7] += w1.w * vo;
    }
}

__global__ __launch_bounds__(THREADS)
void caps_routing_kernel(const float* __restrict__ x,
                         const float* __restrict__ W,
                         float* __restrict__ out) {
    extern __shared__ float sm[];
    float* xs = sm;                       // [Mn][XROW]
    float* bb = xs + XS_FLOATS;           // [Dn][Mn][BROW]
    float* mx = bb + BB_FLOATS;           // [Mn][BROW]
    float* rs = mx + MX_FLOATS;           // [Mn][BROW]

    const int bidx = blockIdx.x;
    const int tid  = threadIdx.x;
    const int d    = tid >> 5;            // 0..9
    const int m    = tid & 31;            // 0..31

    // ---- load x[bidx] into padded smem (coalesced float4) ----
    {
        const float4* xg = (const float4*)(x + (size_t)bidx * (Mn * Pn * In));
        const int row4 = (Pn * In) / 4;   // 72 float4 per row
        for (int idx = tid; idx < Mn * row4; idx += THREADS) {
            int mm = idx / row4;
            int j  = idx - mm * row4;
            ((float4*)(xs + mm * XROW))[j] = xg[idx];
        }
    }
    __syncthreads();

    const float4* Wdm = (const float4*)(W + (size_t)((d * Mn + m) * On) * In); // W[d][m][.][.]
    const float4* xm  = (const float4*)(xs + m * XROW);
    float* brow = bb + (d * Mn + m) * BROW;

    float xc[In], wv[In], v[On];

    // ================= routing iteration 1: c = softmax(0 over d) = 1/D =================
#pragma unroll
    for (int i = 0; i < In; i++) xc[i] = 0.f;
    for (int p = 0; p < Pn; p++) {
        float4 a = xm[2 * p], q = xm[2 * p + 1];
        xc[0] += a.x; xc[1] += a.y; xc[2] += a.z; xc[3] += a.w;
        xc[4] += q.x; xc[5] += q.y; xc[6] += q.z; xc[7] += q.w;
    }
#pragma unroll
    for (int i = 0; i < In; i++) xc[i] *= (1.0f / Dn);

    compute_v(Wdm, xc, v);
    compute_wv(Wdm, v, wv);

    // b = u . v   (initial write; b started at 0)
    for (int p = 0; p < Pn; p++) {
        float4 a = xm[2 * p], q = xm[2 * p + 1];
        brow[p] = a.x * wv[0] + a.y * wv[1] + a.z * wv[2] + a.w * wv[3]
                + q.x * wv[4] + q.y * wv[5] + q.z * wv[6] + q.w * wv[7];
    }
    __syncthreads();

    // ================= softmax over d (axis=1), per (m,p) column =================
    for (int col = tid; col < Mn * Pn; col += THREADS) {
        int cm = col / Pn, cp = col - cm * Pn;
        float bv[Dn];
        float vmax = -1e30f;
#pragma unroll
        for (int dd = 0; dd < Dn; dd++) {
            bv[dd] = bb[(dd * Mn + cm) * BROW + cp];
            vmax = fmaxf(vmax, bv[dd]);
        }
        float ssum = 0.f;
#pragma unroll
        for (int dd = 0; dd < Dn; dd++) ssum += __expf(bv[dd] - vmax);
        mx[cm * BROW + cp] = vmax;
        rs[cm * BROW + cp] = 1.0f / ssum;
    }
    __syncthreads();

    // ================= routing iteration 2 =================
    {
        const float* mxr = mx + m * BROW;
        const float* rsr = rs + m * BROW;
#pragma unroll
        for (int i = 0; i < In; i++) xc[i] = 0.f;
        for (int p = 0; p < Pn; p++) {
            float c = __expf(brow[p] - mxr[p]) * rsr[p];
            float4 a = xm[2 * p], q = xm[2 * p + 1];
            xc[0] += c * a.x; xc[1] += c * a.y; xc[2] += c * a.z; xc[3] += c * a.w;
            xc[4] += c * q.x; xc[5] += c * q.y; xc[6] += c * q.z; xc[7] += c * q.w;
        }
    }
    compute_v(Wdm, xc, v);
    compute_wv(Wdm, v, wv);

    // b += u . v   (own row only — no cross-thread hazard)
    for (int p = 0; p < Pn; p++) {
        float4 a = xm[2 * p], q = xm[2 * p + 1];
        brow[p] += a.x * wv[0] + a.y * wv[1] + a.z * wv[2] + a.w * wv[3]
                 + q.x * wv[4] + q.y * wv[5] + q.z * wv[6] + q.w * wv[7];
    }

    // ================= final: softmax over p (axis=3) fused with xc =================
    {
        float vmax = -1e30f;
        for (int p = 0; p < Pn; p++) vmax = fmaxf(vmax, brow[p]);
        float ssum = 0.f;
        for (int p = 0; p < Pn; p++) ssum += __expf(brow[p] - vmax);
        float rsum = 1.0f / ssum;
#pragma unroll
        for (int i = 0; i < In; i++) xc[i] = 0.f;
        for (int p = 0; p < Pn; p++) {
            float c = __expf(brow[p] - vmax) * rsum;
            float4 a = xm[2 * p], q = xm[2 * p + 1];
            xc[0] += c * a.x; xc[1] += c * a.y; xc[2] += c * a.z; xc[3] += c * a.w;
            xc[4] += c * q.x; xc[5] += c * q.y; xc[6] += c * q.z; xc[7] += c * q.w;
        }
    }
    compute_v(Wdm, xc, v);

    if (m < On)
        out[((size_t)bidx * Dn + d) * On + m] = v[m];
}

extern "C" void kernel_launch(void* const* d_in, const int* in_sizes, int n_in,
                              void* d_out, int out_size) {
    const float* x = (const float*)d_in[0];
    const float* W = (const float*)d_in[1];
    // Defensive: identify by element count (x = 2359296, W = 40960)
    if (n_in >= 2 && in_sizes[0] == Dn * Mn * On * In) {
        x = (const float*)d_in[1];
        W = (const float*)d_in[0];
    }
    float* out = (float*)d_out;

    size_t smem = SMEM_FLOATS * sizeof(float);
    cudaFuncSetAttribute(caps_routing_kernel,
                         cudaFuncAttributeMaxDynamicSharedMemorySize, (int)smem);
    caps_routing_kernel<<<Bn, THREADS, smem>>>(x, W, out);
}

// round 2
// speedup vs baseline: 2.2169x; 2.2169x over previous
#include <cuda_runtime.h>
#include <math.h>

// Problem constants
#define Bn 256
#define Dn 10
#define Mn 32
#define Pn 36
#define In 8
#define On 16

#define THREADS 320            // 10 warps: warp = d, lane = m

// Padded smem layouts (bank-conflict-free):
//  x row stride 292 floats (P*I=288 + 4)
//  b row stride 37 floats  (P=36 + 1)
#define XROW 292
#define BROW 37

#define XS_FLOATS (Mn * XROW)                 // 9344
#define BB_FLOATS (Dn * Mn * BROW)            // 11840
#define MX_FLOATS (Mn * BROW)                 // 1184
#define SMEM_FLOATS (XS_FLOATS + BB_FLOATS + 2 * MX_FLOATS)   // 23552 -> 94208 B

// Transposed W: Wt[d][o][ih][m] as float4  (d:10, o:16, ih:2, m:32) = 10240 float4
// Lane index = m -> contiguous 16B/lane = fully coalesced LDG.128 across the warp.
__device__ float4 Wt_g[Dn * On * 2 * Mn];

__global__ void transpose_W_kernel(const float* __restrict__ W) {
    int idx = blockIdx.x * blockDim.x + threadIdx.x;
    if (idx >= Dn * On * 2 * Mn) return;
    int m  = idx & 31;
    int r  = idx >> 5;
    int ih = r & 1;  r >>= 1;
    int o  = r & 15;
    int d  = r >> 4;
    const float4* Wsrc = (const float4*)W;
    // source: W[d][m][o][i], float4 granules over i
    Wt_g[idx] = Wsrc[((d * Mn + m) * On + o) * 2 + ih];
}

// s[d,o] = sum_m sum_i W[d,m,o,i]*xc[d,m,i]; warp-butterfly reduce over m (lane);
// then squash -> v (every lane ends with the full v[0..15]).
__device__ __forceinline__ void compute_v(int d, int m, const float xc[In], float v[On]) {
    const float4* Wt = Wt_g + (d * On * 2) * Mn + m;
#pragma unroll
    for (int o = 0; o < On; o++) {
        float4 w0 = __ldg(Wt + (2 * o) * Mn);
        float4 w1 = __ldg(Wt + (2 * o + 1) * Mn);
        v[o] = w0.x * xc[0] + w0.y * xc[1] + w0.z * xc[2] + w0.w * xc[3]
             + w1.x * xc[4] + w1.y * xc[5] + w1.z * xc[6] + w1.w * xc[7];
    }
#pragma unroll
    for (int off = 16; off; off >>= 1) {
#pragma unroll
        for (int o = 0; o < On; o++)
            v[o] += __shfl_xor_sync(0xffffffffu, v[o], off);
    }
    float sq = 0.f;
#pragma unroll
    for (int o = 0; o < On; o++) sq += v[o] * v[o];
    // squash: v = (sq/(1+sq)) * s / sqrt(sq + 1e-7)
    float k = sq / ((1.0f + sq) * sqrtf(sq + 1e-7f));
#pragma unroll
    for (int o = 0; o < On; o++) v[o] *= k;
}

// wv[i] = sum_o W[d,m,o,i] * v[o]   (all register-resident, coalesced Wt reads)
__device__ __forceinline__ void compute_wv(int d, int m, const float v[On], float wv[In]) {
    const float4* Wt = Wt_g + (d * On * 2) * Mn + m;
#pragma unroll
    for (int i = 0; i < In; i++) wv[i] = 0.f;
#pragma unroll
    for (int o = 0; o < On; o++) {
        float4 w0 = __ldg(Wt + (2 * o) * Mn);
        float4 w1 = __ldg(Wt + (2 * o + 1) * Mn);
        float vo = v[o];
        wv[0] += w0.x * vo; wv[1] += w0.y * vo; wv[2] += w0.z * vo; wv[3] += w0.w * vo;
        wv[4] += w1.x * vo; wv[5] += w1.y * vo; wv[6] += w1.z * vo; wv[7] += w1.w * vo;
    }
}

__global__ __launch_bounds__(THREADS)
void caps_routing_kernel(const float* __restrict__ x,
                         float* __restrict__ out) {
    extern __shared__ float sm[];
    float* xs = sm;                       // [Mn][XROW]
    float* bb = xs + XS_FLOATS;           // [Dn][Mn][BROW]
    float* mx = bb + BB_FLOATS;           // [Mn][BROW]
    float* rs = mx + MX_FLOATS;           // [Mn][BROW]

    const int bidx = blockIdx.x;
    const int tid  = threadIdx.x;
    const int d    = tid >> 5;            // 0..9
    const int m    = tid & 31;            // 0..31

    // ---- load x[bidx] into padded smem (coalesced float4) ----
    {
        const float4* xg = (const float4*)(x + (size_t)bidx * (Mn * Pn * In));
        const int row4 = (Pn * In) / 4;   // 72 float4 per row
        for (int idx = tid; idx < Mn * row4; idx += THREADS) {
            int mm = idx / row4;
            int j  = idx - mm * row4;
            ((float4*)(xs + mm * XROW))[j] = xg[idx];
        }
    }
    __syncthreads();

    const float4* xm = (const float4*)(xs + m * XROW);
    float* brow = bb + (d * Mn + m) * BROW;

    float xc[In], wv[In], v[On];

    // ================= routing iteration 1: c = softmax(0 over d) = 1/D =================
#pragma unroll
    for (int i = 0; i < In; i++) xc[i] = 0.f;
    for (int p = 0; p < Pn; p++) {
        float4 a = xm[2 * p], q = xm[2 * p + 1];
        xc[0] += a.x; xc[1] += a.y; xc[2] += a.z; xc[3] += a.w;
        xc[4] += q.x; xc[5] += q.y; xc[6] += q.z; xc[7] += q.w;
    }
#pragma unroll
    for (int i = 0; i < In; i++) xc[i] *= (1.0f / Dn);

    compute_v(d, m, xc, v);
    compute_wv(d, m, v, wv);

    // b = u . v   (initial write; b started at 0)
    for (int p = 0; p < Pn; p++) {
        float4 a = xm[2 * p], q = xm[2 * p + 1];
        brow[p] = a.x * wv[0] + a.y * wv[1] + a.z * wv[2] + a.w * wv[3]
                + q.x * wv[4] + q.y * wv[5] + q.z * wv[6] + q.w * wv[7];
    }
    __syncthreads();

    // ================= softmax over d (axis=1), per (m,p) column =================
    for (int col = tid; col < Mn * Pn; col += THREADS) {
        int cm = col / Pn, cp = col - cm * Pn;
        float bv[Dn];
        float vmax = -1e30f;
#pragma unroll
        for (int dd = 0; dd < Dn; dd++) {
            bv[dd] = bb[(dd * Mn + cm) * BROW + cp];
            vmax = fmaxf(vmax, bv[dd]);
        }
        float ssum = 0.f;
#pragma unroll
        for (int dd = 0; dd < Dn; dd++) ssum += __expf(bv[dd] - vmax);
        mx[cm * BROW + cp] = vmax;
        rs[cm * BROW + cp] = 1.0f / ssum;
    }
    __syncthreads();

    // ================= routing iteration 2 =================
    {
        const float* mxr = mx + m * BROW;
        const float* rsr = rs + m * BROW;
#pragma unroll
        for (int i = 0; i < In; i++) xc[i] = 0.f;
        for (int p = 0; p < Pn; p++) {
            float c = __expf(brow[p] - mxr[p]) * rsr[p];
            float4 a = xm[2 * p], q = xm[2 * p + 1];
            xc[0] += c * a.x; xc[1] += c * a.y; xc[2] += c * a.z; xc[3] += c * a.w;
            xc[4] += c * q.x; xc[5] += c * q.y; xc[6] += c * q.z; xc[7] += c * q.w;
        }
    }
    compute_v(d, m, xc, v);
    compute_wv(d, m, v, wv);

    // b += u . v   (own row only — no cross-thread hazard)
    for (int p = 0; p < Pn; p++) {
        float4 a = xm[2 * p], q = xm[2 * p + 1];
        brow[p] += a.x * wv[0] + a.y * wv[1] + a.z * wv[2] + a.w * wv[3]
                 + q.x * wv[4] + q.y * wv[5] + q.z * wv[6] + q.w * wv[7];
    }

    // ================= final: softmax over p (axis=3) fused with xc =================
    {
        float vmax = -1e30f;
        for (int p = 0; p < Pn; p++) vmax = fmaxf(vmax, brow[p]);
        float ssum = 0.f;
        for (int p = 0; p < Pn; p++) ssum += __expf(brow[p] - vmax);
        float rsum = 1.0f / ssum;
#pragma unroll
        for (int i = 0; i < In; i++) xc[i] = 0.f;
        for (int p = 0; p < Pn; p++) {
            float c = __expf(brow[p] - vmax) * rsum;
            float4 a = xm[2 * p], q = xm[2 * p + 1];
            xc[0] += c * a.x; xc[1] += c * a.y; xc[2] += c * a.z; xc[3] += c * a.w;
            xc[4] += c * q.x; xc[5] += c * q.y; xc[6] += c * q.z; xc[7] += c * q.w;
        }
    }
    compute_v(d, m, xc, v);

    if (m < On)
        out[((size_t)bidx * Dn + d) * On + m] = v[m];
}

extern "C" void kernel_launch(void* const* d_in, const int* in_sizes, int n_in,
                              void* d_out, int out_size) {
    const float* x = (const float*)d_in[0];
    const float* W = (const float*)d_in[1];
    // Defensive: identify by element count (x = 2359296, W = 40960)
    if (n_in >= 2 && in_sizes[0] == Dn * Mn * On * In) {
        x = (const float*)d_in[1];
        W = (const float*)d_in[0];
    }
    float* out = (float*)d_out;

    // One-time (per launch) W transpose into coalesced layout
    transpose_W_kernel<<<(Dn * On * 2 * Mn + 255) / 256, 256>>>(W);

    size_t smem = SMEM_FLOATS * sizeof(float);
    cudaFuncSetAttribute(caps_routing_kernel,
                         cudaFuncAttributeMaxDynamicSharedMemorySize, (int)smem);
    caps_routing_kernel<<<Bn, THREADS, smem>>>(x, out);
}

// round 3
// speedup vs baseline: 2.6205x; 1.1821x over previous
#include <cuda_runtime.h>
#include <math.h>

// Problem constants
#define Bn 256
#define Dn 10
#define Mn 32
#define Pn 36
#define In 8
#define On 16

#define THREADS 320            // 10 warps: warp = d, lane = m

// Padded smem layouts (bank-conflict-free):
//  x row stride 292 floats (P*I=288 + 4)
//  b row stride 37 floats  (P=36 + 1)
#define XROW 292
#define BROW 37

#define XS_FLOATS (Mn * XROW)                 // 9344
#define BB_FLOATS (Dn * Mn * BROW)            // 11840
#define MX_FLOATS (Mn * BROW)                 // 1184
#define SMEM_FLOATS (XS_FLOATS + BB_FLOATS + 2 * MX_FLOATS)   // 23552 -> 94208 B

// Transposed W: Wt[d][o][ih][m] as float4  (d:10, o:16, ih:2, m:32) = 10240 float4
__device__ float4 Wt_g[Dn * On * 2 * Mn];

__global__ void transpose_W_kernel(const float* __restrict__ W) {
    int idx = blockIdx.x * blockDim.x + threadIdx.x;
    if (idx >= Dn * On * 2 * Mn) return;
    int m  = idx & 31;
    int r  = idx >> 5;
    int ih = r & 1;  r >>= 1;
    int o  = r & 15;
    int d  = r >> 4;
    const float4* Wsrc = (const float4*)W;
    Wt_g[idx] = Wsrc[((d * Mn + m) * On + o) * 2 + ih];
}

// Distributed compute_v:
// per-lane partials v[o] for its m, then DECIMATED reduction over lanes (16 shfl),
// duplicate-sum on bit0, squash. Returns s[o]*k where o = (m>>1)&15.
__device__ __forceinline__ float compute_v_dist(int d, int m, const float xc[In]) {
    const float4* Wt = Wt_g + (d * On * 2) * Mn + m;
    float v[On];
#pragma unroll
    for (int o = 0; o < On; o++) {
        float4 w0 = __ldg(Wt + (2 * o) * Mn);
        float4 w1 = __ldg(Wt + (2 * o + 1) * Mn);
        v[o] = w0.x * xc[0] + w0.y * xc[1] + w0.z * xc[2] + w0.w * xc[3]
             + w1.x * xc[4] + w1.y * xc[5] + w1.z * xc[6] + w1.w * xc[7];
    }
    // round 1: xor 16 -> 8 values; hi lanes keep upper o-half
    bool h = (m & 16);
    float a8[8];
#pragma unroll
    for (int j = 0; j < 8; j++) {
        float send = h ? v[j] : v[j + 8];
        float keep = h ? v[j + 8] : v[j];
        a8[j] = keep + __shfl_xor_sync(0xffffffffu, send, 16);
    }
    // round 2: xor 8 -> 4
    h = (m & 8);
    float a4[4];
#pragma unroll
    for (int j = 0; j < 4; j++) {
        float send = h ? a8[j] : a8[j + 4];
        float keep = h ? a8[j + 4] : a8[j];
        a4[j] = keep + __shfl_xor_sync(0xffffffffu, send, 8);
    }
    // round 3: xor 4 -> 2
    h = (m & 4);
    float a2[2];
#pragma unroll
    for (int j = 0; j < 2; j++) {
        float send = h ? a4[j] : a4[j + 2];
        float keep = h ? a4[j + 2] : a4[j];
        a2[j] = keep + __shfl_xor_sync(0xffffffffu, send, 4);
    }
    // round 4: xor 2 -> 1
    h = (m & 2);
    float send = h ? a2[0] : a2[1];
    float keep = h ? a2[1] : a2[0];
    float s1 = keep + __shfl_xor_sync(0xffffffffu, send, 2);
    // round 5: xor 1 (duplicate-sum; lanes 2o and 2o+1 now both hold s[o])
    s1 += __shfl_xor_sync(0xffffffffu, s1, 1);

    // squash: sq = sum over 16 distinct o (butterfly over masks 2,4,8,16 stays
    // inside the bit0-coset, hitting each o exactly once)
    float sq = s1 * s1;
    sq += __shfl_xor_sync(0xffffffffu, sq, 2);
    sq += __shfl_xor_sync(0xffffffffu, sq, 4);
    sq += __shfl_xor_sync(0xffffffffu, sq, 8);
    sq += __shfl_xor_sync(0xffffffffu, sq, 16);
    float k = sq / ((1.0f + sq) * sqrtf(sq + 1e-7f));
    return s1 * k;
}

// Broadcast distributed v to all lanes: v[o] lives on lane 2*o.
__device__ __forceinline__ void bcast_v(float vd, float vo[On]) {
#pragma unroll
    for (int o = 0; o < On; o++)
        vo[o] = __shfl_sync(0xffffffffu, vd, 2 * o);
}

// wv[i] = sum_o W[d,m,o,i] * v[o]
__device__ __forceinline__ void compute_wv(int d, int m, const float vo[On], float wv[In]) {
    const float4* Wt = Wt_g + (d * On * 2) * Mn + m;
#pragma unroll
    for (int i = 0; i < In; i++) wv[i] = 0.f;
#pragma unroll
    for (int o = 0; o < On; o++) {
        float4 w0 = __ldg(Wt + (2 * o) * Mn);
        float4 w1 = __ldg(Wt + (2 * o + 1) * Mn);
        float v = vo[o];
        wv[0] += w0.x * v; wv[1] += w0.y * v; wv[2] += w0.z * v; wv[3] += w0.w * v;
        wv[4] += w1.x * v; wv[5] += w1.y * v; wv[6] += w1.z * v; wv[7] += w1.w * v;
    }
}

__global__ __launch_bounds__(THREADS, 2)
void caps_routing_kernel(const float* __restrict__ x,
                         float* __restrict__ out) {
    extern __shared__ float sm[];
    float* xs = sm;                       // [Mn][XROW]
    float* bb = xs + XS_FLOATS;           // [Dn][Mn][BROW]
    float* mx = bb + BB_FLOATS;           // [Mn][BROW]  (also xsum scratch early)
    float* rs = mx + MX_FLOATS;           // [Mn][BROW]

    const int bidx = blockIdx.x;
    const int tid  = threadIdx.x;
    const int d    = tid >> 5;            // 0..9
    const int m    = tid & 31;            // 0..31

    // ---- load x[bidx] into padded smem (coalesced float4) ----
    {
        const float4* xg = (const float4*)(x + (size_t)bidx * (Mn * Pn * In));
        const int row4 = (Pn * In) / 4;   // 72
        for (int idx = tid; idx < Mn * row4; idx += THREADS) {
            int mm = idx / row4;
            int j  = idx - mm * row4;
            ((float4*)(xs + mm * XROW))[j] = xg[idx];
        }
    }
    __syncthreads();

    // ---- cooperative xsum[m][i] = (1/D) * sum_p x[m,p,i] (d-independent) ----
    if (tid < Mn * In) {
        int mm = tid >> 3, ii = tid & 7;
        const float* xr = xs + mm * XROW + ii;
        float s = 0.f;
#pragma unroll
        for (int p = 0; p < Pn; p++) s += xr[8 * p];
        mx[mm * 9 + ii] = s * (1.0f / Dn);   // padded stride 9 (conflict-free reads)
    }
    __syncthreads();

    const float4* xm = (const float4*)(xs + m * XROW);
    float* brow = bb + (d * Mn + m) * BROW;

    float xc[In], wv[In], vo[On];

    // ================= routing iteration 1: c = 1/D (shared xsum) =================
#pragma unroll
    for (int i = 0; i < In; i++) xc[i] = mx[m * 9 + i];

    float vd = compute_v_dist(d, m, xc);
    bcast_v(vd, vo);
    compute_wv(d, m, vo, wv);

    // b = u . v  (initial write)
    for (int p = 0; p < Pn; p++) {
        float4 a = xm[2 * p], q = xm[2 * p + 1];
        brow[p] = a.x * wv[0] + a.y * wv[1] + a.z * wv[2] + a.w * wv[3]
                + q.x * wv[4] + q.y * wv[5] + q.z * wv[6] + q.w * wv[7];
    }
    __syncthreads();

    // ================= softmax over d (axis=1), per (m,p) column =================
    for (int col = tid; col < Mn * Pn; col += THREADS) {
        int cm = col / Pn, cp = col - cm * Pn;
        float bv[Dn];
        float vmax = -1e30f;
#pragma unroll
        for (int dd = 0; dd < Dn; dd++) {
            bv[dd] = bb[(dd * Mn + cm) * BROW + cp];
            vmax = fmaxf(vmax, bv[dd]);
        }
        float ssum = 0.f;
#pragma unroll
        for (int dd = 0; dd < Dn; dd++) ssum += __expf(bv[dd] - vmax);
        mx[cm * BROW + cp] = vmax;
        rs[cm * BROW + cp] = 1.0f / ssum;
    }
    __syncthreads();

    // ================= routing iteration 2 =================
    {
        const float* mxr = mx + m * BROW;
        const float* rsr = rs + m * BROW;
#pragma unroll
        for (int i = 0; i < In; i++) xc[i] = 0.f;
        for (int p = 0; p < Pn; p++) {
            float c = __expf(brow[p] - mxr[p]) * rsr[p];
            float4 a = xm[2 * p], q = xm[2 * p + 1];
            xc[0] += c * a.x; xc[1] += c * a.y; xc[2] += c * a.z; xc[3] += c * a.w;
            xc[4] += c * q.x; xc[5] += c * q.y; xc[6] += c * q.z; xc[7] += c * q.w;
        }
    }
    vd = compute_v_dist(d, m, xc);
    bcast_v(vd, vo);
    compute_wv(d, m, vo, wv);

    // ====== FUSED: b += u.v  +  softmax over p  +  weighted x accumulation ======
    // (axis-3 softmax is thread-local -> online rescaling, single x pass)
    {
        float M = -1e30f, Z = 0.f;
        float acc[In];
#pragma unroll
        for (int i = 0; i < In; i++) acc[i] = 0.f;
        for (int p = 0; p < Pn; p++) {
            float4 a = xm[2 * p], q = xm[2 * p + 1];
            float bnew = brow[p]
                       + a.x * wv[0] + a.y * wv[1] + a.z * wv[2] + a.w * wv[3]
                       + q.x * wv[4] + q.y * wv[5] + q.z * wv[6] + q.w * wv[7];
            float Mn2 = fmaxf(M, bnew);
            float scale = __expf(M - Mn2);
            float w = __expf(bnew - Mn2);
            Z = Z * scale + w;
            acc[0] = acc[0] * scale + w * a.x;
            acc[1] = acc[1] * scale + w * a.y;
            acc[2] = acc[2] * scale + w * a.z;
            acc[3] = acc[3] * scale + w * a.w;
            acc[4] = acc[4] * scale + w * q.x;
            acc[5] = acc[5] * scale + w * q.y;
            acc[6] = acc[6] * scale + w * q.z;
            acc[7] = acc[7] * scale + w * q.w;
            M = Mn2;
        }
        float rz = 1.0f / Z;
#pragma unroll
        for (int i = 0; i < In; i++) xc[i] = acc[i] * rz;
    }
    vd = compute_v_dist(d, m, xc);

    // lane 2*o holds final v[o]
    if (!(m & 1))
        out[((size_t)bidx * Dn + d) * On + (m >> 1)] = vd;
}

extern "C" void kernel_launch(void* const* d_in, const int* in_sizes, int n_in,
                              void* d_out, int out_size) {
    const float* x = (const float*)d_in[0];
    const float* W = (const float*)d_in[1];
    if (n_in >= 2 && in_sizes[0] == Dn * Mn * On * In) {
        x = (const float*)d_in[1];
        W = (const float*)d_in[0];
    }
    float* out = (float*)d_out;

    transpose_W_kernel<<<(Dn * On * 2 * Mn + 255) / 256, 256>>>(W);

    size_t smem = SMEM_FLOATS * sizeof(float);
    cudaFuncSetAttribute(caps_routing_kernel,
                         cudaFuncAttributeMaxDynamicSharedMemorySize, (int)smem);
    caps_routing_kernel<<<Bn, THREADS, smem>>>(x, out);
}

// round 4
// speedup vs baseline: 2.8246x; 1.0779x over previous
#include <cuda_runtime.h>
#include <math.h>

// Problem constants
#define Bn 256
#define Dn 10
#define Mn 32
#define Pn 36
#define In 8
#define On 16

#define THREADS 320            // 10 warps: warp = d, lane = m

// x smem row stride (P*I=288 + 4 pad) -> conflict-free LDS.128
#define XROW 292
#define XS_FLOATS (Mn * XROW)           // 9344
#define WVS_FLOATS (Dn * Mn * In)       // 2560
#define CSROW 37                        // float2 row stride for stats (pad)
#define CS_FLOAT2S (Mn * CSROW)         // 1184
#define SMEM_FLOATS (XS_FLOATS + WVS_FLOATS + 2 * CS_FLOAT2S)   // 14272 -> 57088 B

// Transposed W: Wt[d][o][ih][m] as float4 -> coalesced LDG.128 over lane m
__device__ float4 Wt_g[Dn * On * 2 * Mn];

__global__ void transpose_W_kernel(const float* __restrict__ W) {
    int idx = blockIdx.x * blockDim.x + threadIdx.x;
    if (idx >= Dn * On * 2 * Mn) return;
    int m  = idx & 31;
    int r  = idx >> 5;
    int ih = r & 1;  r >>= 1;
    int o  = r & 15;
    int d  = r >> 4;
    const float4* Wsrc = (const float4*)W;
    Wt_g[idx] = Wsrc[((d * Mn + m) * On + o) * 2 + ih];
}

// Distributed compute_v: per-lane partials, decimated lane reduction (16 shfl),
// squash. Returns s[o]*k on lanes 2o and 2o+1 (o = m>>1).
__device__ __forceinline__ float compute_v_dist(int d, int m, const float xc[In]) {
    const float4* Wt = Wt_g + (d * On * 2) * Mn + m;
    float v[On];
#pragma unroll
    for (int o = 0; o < On; o++) {
        float4 w0 = __ldg(Wt + (2 * o) * Mn);
        float4 w1 = __ldg(Wt + (2 * o + 1) * Mn);
        v[o] = w0.x * xc[0] + w0.y * xc[1] + w0.z * xc[2] + w0.w * xc[3]
             + w1.x * xc[4] + w1.y * xc[5] + w1.z * xc[6] + w1.w * xc[7];
    }
    bool h = (m & 16);
    float a8[8];
#pragma unroll
    for (int j = 0; j < 8; j++) {
        float send = h ? v[j] : v[j + 8];
        float keep = h ? v[j + 8] : v[j];
        a8[j] = keep + __shfl_xor_sync(0xffffffffu, send, 16);
    }
    h = (m & 8);
    float a4[4];
#pragma unroll
    for (int j = 0; j < 4; j++) {
        float send = h ? a8[j] : a8[j + 4];
        float keep = h ? a8[j + 4] : a8[j];
        a4[j] = keep + __shfl_xor_sync(0xffffffffu, send, 8);
    }
    h = (m & 4);
    float a2[2];
#pragma unroll
    for (int j = 0; j < 2; j++) {
        float send = h ? a4[j] : a4[j + 2];
        float keep = h ? a4[j + 2] : a4[j];
        a2[j] = keep + __shfl_xor_sync(0xffffffffu, send, 4);
    }
    h = (m & 2);
    float send = h ? a2[0] : a2[1];
    float keep = h ? a2[1] : a2[0];
    float s1 = keep + __shfl_xor_sync(0xffffffffu, send, 2);
    s1 += __shfl_xor_sync(0xffffffffu, s1, 1);

    float sq = s1 * s1;
    sq += __shfl_xor_sync(0xffffffffu, sq, 2);
    sq += __shfl_xor_sync(0xffffffffu, sq, 4);
    sq += __shfl_xor_sync(0xffffffffu, sq, 8);
    sq += __shfl_xor_sync(0xffffffffu, sq, 16);
    float k = sq / ((1.0f + sq) * sqrtf(sq + 1e-7f));
    return s1 * k;
}

__device__ __forceinline__ void bcast_v(float vd, float vo[On]) {
#pragma unroll
    for (int o = 0; o < On; o++)
        vo[o] = __shfl_sync(0xffffffffu, vd, 2 * o);
}

__device__ __forceinline__ void compute_wv(int d, int m, const float vo[On], float wv[In]) {
    const float4* Wt = Wt_g + (d * On * 2) * Mn + m;
#pragma unroll
    for (int i = 0; i < In; i++) wv[i] = 0.f;
#pragma unroll
    for (int o = 0; o < On; o++) {
        float4 w0 = __ldg(Wt + (2 * o) * Mn);
        float4 w1 = __ldg(Wt + (2 * o + 1) * Mn);
        float v = vo[o];
        wv[0] += w0.x * v; wv[1] += w0.y * v; wv[2] += w0.z * v; wv[3] += w0.w * v;
        wv[4] += w1.x * v; wv[5] += w1.y * v; wv[6] += w1.z * v; wv[7] += w1.w * v;
    }
}

__device__ __forceinline__ float dot8(const float4 a, const float4 q, const float w[In]) {
    return a.x * w[0] + a.y * w[1] + a.z * w[2] + a.w * w[3]
         + q.x * w[4] + q.y * w[5] + q.z * w[6] + q.w * w[7];
}

__global__ __launch_bounds__(THREADS, 2)
void caps_routing_kernel(const float* __restrict__ x,
                         float* __restrict__ out) {
    extern __shared__ float sm[];
    float*  xs  = sm;                          // [Mn][XROW]
    float*  wvs = xs + XS_FLOATS;              // [Dn*Mn][8]
    float2* cs  = (float2*)(wvs + WVS_FLOATS); // [Mn][CSROW] (mx, rs)
    float*  xsum = (float*)cs;                 // early overlap: [Mn][9]

    const int bidx = blockIdx.x;
    const int tid  = threadIdx.x;
    const int d    = tid >> 5;
    const int m    = tid & 31;

    // ---- load x[bidx] into padded smem (coalesced float4) ----
    {
        const float4* xg = (const float4*)(x + (size_t)bidx * (Mn * Pn * In));
        const int row4 = (Pn * In) / 4;   // 72
        for (int idx = tid; idx < Mn * row4; idx += THREADS) {
            int mm = idx / row4;
            int j  = idx - mm * row4;
            ((float4*)(xs + mm * XROW))[j] = xg[idx];
        }
    }
    __syncthreads();

    // ---- cooperative xsum[m][i] = (1/D) * sum_p x[m,p,i] ----
    if (tid < Mn * In) {
        int mm = tid >> 3, ii = tid & 7;
        const float* xr = xs + mm * XROW + ii;
        float s = 0.f;
#pragma unroll
        for (int p = 0; p < Pn; p++) s += xr[8 * p];
        xsum[mm * 9 + ii] = s * (1.0f / Dn);
    }
    __syncthreads();

    const float4* xm = (const float4*)(xs + m * XROW);

    float xc[In], wv1[In], wv2[In], vo[On];

    // ================= iteration 1: c = 1/D =================
#pragma unroll
    for (int i = 0; i < In; i++) xc[i] = xsum[m * 9 + i];

    float vd = compute_v_dist(d, m, xc);
    bcast_v(vd, vo);
    compute_wv(d, m, vo, wv1);

    // publish wv1 for cross-d softmax stats
    {
        float4* w4 = (float4*)(wvs + (d * Mn + m) * In);
        w4[0] = make_float4(wv1[0], wv1[1], wv1[2], wv1[3]);
        w4[1] = make_float4(wv1[4], wv1[5], wv1[6], wv1[7]);
    }
    __syncthreads();

    // ===== axis-1 (d) softmax stats per (m,p): b[d] = x_p . wv1[d,m] =====
    for (int col = tid; col < Mn * Pn; col += THREADS) {
        int cm = col / Pn, cp = col - cm * Pn;
        float4 xa = *(const float4*)(xs + cm * XROW + 8 * cp);
        float4 xq = *(const float4*)(xs + cm * XROW + 8 * cp + 4);
        float bv[Dn];
        float vmax = -1e30f;
#pragma unroll
        for (int dd = 0; dd < Dn; dd++) {
            const float4* w4 = (const float4*)(wvs + (dd * Mn + cm) * In);
            float4 wa = w4[0], wb = w4[1];
            float b = xa.x * wa.x + xa.y * wa.y + xa.z * wa.z + xa.w * wa.w
                    + xq.x * wb.x + xq.y * wb.y + xq.z * wb.z + xq.w * wb.w;
            bv[dd] = b;
            vmax = fmaxf(vmax, b);
        }
        float ssum = 0.f;
#pragma unroll
        for (int dd = 0; dd < Dn; dd++) ssum += __expf(bv[dd] - vmax);
        cs[cm * CSROW + cp] = make_float2(vmax, 1.0f / ssum);
    }
    __syncthreads();

    // ================= iteration 2 (b recomputed on the fly) =================
    {
        const float2* csr = cs + m * CSROW;
#pragma unroll
        for (int i = 0; i < In; i++) xc[i] = 0.f;
        for (int p = 0; p < Pn; p++) {
            float4 a = xm[2 * p], q = xm[2 * p + 1];
            float2 st = csr[p];
            float b = dot8(a, q, wv1);
            float c = __expf(b - st.x) * st.y;
            xc[0] += c * a.x; xc[1] += c * a.y; xc[2] += c * a.z; xc[3] += c * a.w;
            xc[4] += c * q.x; xc[5] += c * q.y; xc[6] += c * q.z; xc[7] += c * q.w;
        }
    }
    vd = compute_v_dist(d, m, xc);
    bcast_v(vd, vo);
    compute_wv(d, m, vo, wv2);

    // combined: b_final(p) = x_p . (wv1 + wv2)
    float wvt[In];
#pragma unroll
    for (int i = 0; i < In; i++) wvt[i] = wv1[i] + wv2[i];

    // ===== FUSED: axis-3 softmax (thread-local, online) + weighted x acc =====
    {
        float M = -1e30f, Z = 0.f;
        float acc[In];
#pragma unroll
        for (int i = 0; i < In; i++) acc[i] = 0.f;
        for (int p = 0; p < Pn; p++) {
            float4 a = xm[2 * p], q = xm[2 * p + 1];
            float bnew = dot8(a, q, wvt);
            float M2 = fmaxf(M, bnew);
            float scale = __expf(M - M2);
            float w = __expf(bnew - M2);
            Z = Z * scale + w;
            acc[0] = acc[0] * scale + w * a.x;
            acc[1] = acc[1] * scale + w * a.y;
            acc[2] = acc[2] * scale + w * a.z;
            acc[3] = acc[3] * scale + w * a.w;
            acc[4] = acc[4] * scale + w * q.x;
            acc[5] = acc[5] * scale + w * q.y;
            acc[6] = acc[6] * scale + w * q.z;
            acc[7] = acc[7] * scale + w * q.w;
            M = M2;
        }
        float rz = 1.0f / Z;
#pragma unroll
        for (int i = 0; i < In; i++) xc[i] = acc[i] * rz;
    }
    vd = compute_v_dist(d, m, xc);

    if (!(m & 1))
        out[((size_t)bidx * Dn + d) * On + (m >> 1)] = vd;
}

extern "C" void kernel_launch(void* const* d_in, const int* in_sizes, int n_in,
                              void* d_out, int out_size) {
    const float* x = (const float*)d_in[0];
    const float* W = (const float*)d_in[1];
    if (n_in >= 2 && in_sizes[0] == Dn * Mn * On * In) {
        x = (const float*)d_in[1];
        W = (const float*)d_in[0];
    }
    float* out = (float*)d_out;

    transpose_W_kernel<<<(Dn * On * 2 * Mn + 255) / 256, 256>>>(W);

    size_t smem = SMEM_FLOATS * sizeof(float);
    cudaFuncSetAttribute(caps_routing_kernel,
                         cudaFuncAttributeMaxDynamicSharedMemorySize, (int)smem);
    caps_routing_kernel<<<Bn, THREADS, smem>>>(x, out);
}